// round 14
// baseline (speedup 1.0000x reference)
#include <cuda_runtime.h>
#include <cuda_fp16.h>
#include <cstdint>

// Problem dims
#define KDIM 2304   // Q*BLOCK = 36*64
#define NDIM 512    // P*BLOCK
#define MDIM 8192   // B * 1024 rows
#define NCHUNKS 36  // KDIM / 64
#define ABATCH 2359296  // 1024 * 2304 elements per batch in A

// ---------------- device scratch (allocation-free rule) ----------------------
__device__ __align__(16) __half g_A[(size_t)MDIM * KDIM];   // 37.7 MB
__device__ __align__(16) __half g_W[(size_t)NDIM * KDIM];   // 2.36 MB

// ---------------- PTX helpers (baseline ISA only: sm_80+) --------------------
static __device__ __forceinline__ uint32_t smem_u32(const void* p) {
    uint32_t a;
    asm("{ .reg .u64 t; cvta.to.shared.u64 t, %1; cvt.u32.u64 %0, t; }"
        : "=r"(a) : "l"(p));
    return a;
}

static __device__ __forceinline__ void cpa16(uint32_t sa, const void* ga) {
    asm volatile("cp.async.cg.shared.global [%0], [%1], 16;"
                 :: "r"(sa), "l"(ga) : "memory");
}
#define CP_COMMIT() asm volatile("cp.async.commit_group;" ::: "memory")
#define CP_WAIT(n)  asm volatile("cp.async.wait_group %0;" :: "n"(n) : "memory")

static __device__ __forceinline__ void ldsm_x4(uint32_t* r, uint32_t addr) {
    asm volatile("ldmatrix.sync.aligned.m8n8.x4.shared.b16 {%0,%1,%2,%3}, [%4];"
                 : "=r"(r[0]), "=r"(r[1]), "=r"(r[2]), "=r"(r[3]) : "r"(addr));
}

static __device__ __forceinline__ void mma_fp16(float* d, const uint32_t* a, const uint32_t* b) {
    asm volatile(
        "mma.sync.aligned.m16n8k16.row.col.f32.f16.f16.f32 "
        "{%0,%1,%2,%3}, {%4,%5,%6,%7}, {%8,%9}, {%0,%1,%2,%3};"
        : "+f"(d[0]), "+f"(d[1]), "+f"(d[2]), "+f"(d[3])
        : "r"(a[0]), "r"(a[1]), "r"(a[2]), "r"(a[3]), "r"(b[0]), "r"(b[1]));
}

// ---------------- kernel 1: A build as shifted-image copies + W expand -------
// Key identity: per batch, A_flat[f*1024 + l] = U[f][l], and U[ci*9 + p] is the
// image x[b][ci] shifted by (di-1, dj-1) with zero borders.  No index math.
// Blocks [0, 2048)        : (b, ci) image -> 9 shifted fp16 copies
// Blocks [2048, 2048+512) : W row n = blk - 2048
__global__ void __launch_bounds__(288) build_aw_kernel(
    const float* __restrict__ x, const float* __restrict__ w)
{
    const int tt = threadIdx.x;
    if (blockIdx.x < 2048) {
        __shared__ float s_img[1024];
        const int b = blockIdx.x >> 8, ci = blockIdx.x & 255;
        if (tt < 256)
            *(float4*)&s_img[tt * 4] =
                *(const float4*)(x + ((((size_t)b << 8) + ci) << 10) + tt * 4);
        __syncthreads();

        const int p = tt >> 5;              // 0..8 shift pair
        const int hh = tt & 31;             // output row
        const int di = (p * 11) >> 5;       // p/3
        const int dj = p - di * 3;
        const int f = ci * 9 + p;
        const int sr = hh + di - 1;         // source row

        __half hv[32];
        if ((unsigned)sr < 32u) {
            const float* srow = s_img + (sr << 5);
#pragma unroll
            for (int ww = 0; ww < 32; ww++) {
                int sc = ww + dj - 1;
                float v = ((unsigned)sc < 32u) ? srow[sc] : 0.f;
                hv[ww] = __float2half_rn(v);
            }
        } else {
#pragma unroll
            for (int ww = 0; ww < 32; ww++) hv[ww] = __float2half_rn(0.f);
        }
        uint4* dst = (uint4*)(g_A + (size_t)b * ABATCH + (size_t)f * 1024 + (hh << 5));
#pragma unroll
        for (int qx = 0; qx < 4; qx++) dst[qx] = ((uint4*)hv)[qx];
    } else {
        const int n = blockIdx.x - 2048;     // 0..511
        const int q = tt >> 3;               // k-block index 0..35
        const int kk0 = (tt & 7) * 8;        // k within block, 8 at a time
        const int p = n >> 6, nn = n & 63;
        const float* wb = w + (p * 36 + q) * 64;
        __half2 h[4];
#pragma unroll
        for (int e = 0; e < 4; e++) {
            float v0 = wb[(nn - (kk0 + 2 * e)) & 63];
            float v1 = wb[(nn - (kk0 + 2 * e + 1)) & 63];
            h[e] = __floats2half2_rn(v0, v1);
        }
        *(uint4*)(g_W + (size_t)n * KDIM + q * 64 + kk0) = *(uint4*)h;
    }
}

// ---------------- kernel 2: single fp16 mma.sync GEMM (R8 best config) -------
// C[8192,512] = A * W^T.  CTA tile 128x128, K-chunk 64, 256 threads
// (8 warps, warp grid 4x2, warp tile 32x64).  3-stage cp.async pipeline,
// one barrier per chunk.  2 CTAs/SM.
#define OFF_A 0
#define OFF_B 16384
#define STAGE_BYTES 32768
#define NSTAGE 3
#define SMEM_DYN (NSTAGE * STAGE_BYTES + 1024)   // 99328

// smem rows of 64 fp16 = 128B, XOR-swizzled at 16B granularity:
//   phys(row, kb) = row*128 + ((kb ^ (row & 7)) << 4),  kb = 0..7
static __device__ __forceinline__ void load_stage(
    uint32_t sb,
    const __half* __restrict__ gA, const __half* __restrict__ gB,
    int chunk, int tid)
{
    const int ko = chunk * 64;
#pragma unroll
    for (int it = 0; it < 4; it++) {          // A: 128 rows x 8 chunks = 1024
        int i = it * 256 + tid;
        int row = i >> 3, kb = i & 7;
        uint32_t soff = (uint32_t)(row * 128 + ((kb ^ (row & 7)) << 4));
        cpa16(sb + OFF_A + soff, gA + (size_t)row * KDIM + ko + kb * 8);
    }
#pragma unroll
    for (int it = 0; it < 4; it++) {          // B: 128 rows x 8 chunks = 1024
        int i = it * 256 + tid;
        int row = i >> 3, kb = i & 7;
        uint32_t soff = (uint32_t)(row * 128 + ((kb ^ (row & 7)) << 4));
        cpa16(sb + OFF_B + soff, gB + (size_t)row * KDIM + ko + kb * 8);
    }
}

__global__ void __launch_bounds__(256, 2) gemm_kernel(float* __restrict__ out)
{
    extern __shared__ char dsm[];
    const int tid = threadIdx.x, wid = tid >> 5, lid = tid & 31;
    const int mtile = blockIdx.x;   // 0..63
    const int ntile = blockIdx.y;   // 0..3
    const int wm = wid & 3;         // m-quadrant: rows wm*32..+32
    const int wn = wid >> 2;        // n-half: cols wn*64..+64

    uint32_t dyn_base = smem_u32(dsm);
    uint32_t sm0 = (dyn_base + 1023u) & ~1023u;   // 1KB align

    const __half* gA = g_A + (size_t)mtile * 128 * KDIM;
    const __half* gB = g_W + (size_t)ntile * 128 * KDIM;

    float acc[2][8][4];
#pragma unroll
    for (int a = 0; a < 2; a++)
#pragma unroll
        for (int b = 0; b < 8; b++)
#pragma unroll
            for (int c = 0; c < 4; c++) acc[a][b][c] = 0.f;

    // ldmatrix lane addressing (fixed per thread)
    const int rowA_l = (lid & 15);                     // + wm*32 + mt*16
    const int halfA  = lid >> 4;
    const int rowB_l = (lid & 7) + ((lid & 16) >> 1);  // + wn*64 + g*16
    const int halfB  = (lid >> 3) & 1;

    // prologue: prefetch chunks 0 and 1
    load_stage(sm0, gA, gB, 0, tid);
    CP_COMMIT();
    load_stage(sm0 + STAGE_BYTES, gA, gB, 1, tid);
    CP_COMMIT();

    int stage = 0;
    for (int i = 0; i < NCHUNKS; i++) {
        if (i < NCHUNKS - 1) CP_WAIT(1); else CP_WAIT(0);
        __syncthreads();   // buffer i published; also protects stage reloaded below

        // prefetch chunk i+2 into the stage last read at iteration i-1
        if (i + 2 < NCHUNKS) {
            int ps = stage + 2; if (ps >= NSTAGE) ps -= NSTAGE;
            load_stage(sm0 + (uint32_t)ps * STAGE_BYTES, gA, gB, i + 2, tid);
            CP_COMMIT();
        }

        const uint32_t sb = sm0 + (uint32_t)stage * STAGE_BYTES;
        const uint32_t baseA = sb + OFF_A, baseB = sb + OFF_B;

#pragma unroll
        for (int j = 0; j < 4; j++) {
            uint32_t aF[2][4], bF[4][4];
#pragma unroll
            for (int mt = 0; mt < 2; mt++) {
                int row = wm * 32 + mt * 16 + rowA_l;
                ldsm_x4(aF[mt], baseA + row * 128 + (((j * 2 + halfA) ^ (row & 7)) << 4));
            }
#pragma unroll
            for (int g = 0; g < 4; g++) {
                int row = wn * 64 + g * 16 + rowB_l;
                ldsm_x4(bF[g], baseB + row * 128 + (((j * 2 + halfB) ^ (row & 7)) << 4));
            }
#pragma unroll
            for (int mt = 0; mt < 2; mt++)
#pragma unroll
                for (int nt = 0; nt < 8; nt++)
                    mma_fp16(acc[mt][nt], aF[mt], &bF[nt >> 1][(nt & 1) * 2]);
        }

        if (++stage == NSTAGE) stage = 0;
    }

    // ---------------- epilogue: direct transpose scatter ----------------------
    const int lr = lid >> 2, lc = (lid & 3) * 2;
#pragma unroll
    for (int mt = 0; mt < 2; mt++) {
#pragma unroll
        for (int part = 0; part < 2; part++) {
            int m = mtile * 128 + wm * 32 + mt * 16 + part * 8 + lr;
            int b = m >> 10, pix = m & 1023;
            float* ob = out + ((size_t)b << 19) + pix;   // + o*1024 per output chan
#pragma unroll
            for (int nt = 0; nt < 8; nt++) {
                int o = ntile * 128 + wn * 64 + nt * 8 + lc;
                ob[(size_t)o << 10]       = acc[mt][nt][part * 2 + 0];
                ob[(size_t)(o + 1) << 10] = acc[mt][nt][part * 2 + 1];
            }
        }
    }
}

// ---------------- launch -----------------------------------------------------
extern "C" void kernel_launch(void* const* d_in, const int* in_sizes, int n_in,
                              void* d_out, int out_size)
{
    const float* x = (const float*)d_in[0];   // (8,256,32,32)
    const float* w = (const float*)d_in[1];   // (8,36,64)
    float* out = (float*)d_out;               // (8,512,32,32)

    cudaFuncSetAttribute(gemm_kernel, cudaFuncAttributeMaxDynamicSharedMemorySize, SMEM_DYN);

    build_aw_kernel<<<2048 + NDIM, 288>>>(x, w);
    gemm_kernel<<<dim3(64, 4), 256, SMEM_DYN>>>(out);
}

// round 15
// speedup vs baseline: 1.8048x; 1.8048x over previous
#include <cuda_runtime.h>
#include <cuda_fp16.h>
#include <cstdint>

// Problem dims
#define KDIM 2304   // Q*BLOCK = 36*64
#define NDIM 512    // P*BLOCK
#define MDIM 8192   // B * 1024 rows
#define NCHUNKS 36  // KDIM / 64
#define ABATCH 2359296  // 1024 * 2304 elements per batch in A

// ---------------- device scratch (allocation-free rule) ----------------------
__device__ __align__(16) __half g_A[(size_t)MDIM * KDIM];   // 37.7 MB
__device__ __align__(16) __half g_W[(size_t)NDIM * KDIM];   // 2.36 MB

// ---------------- PTX helpers (baseline ISA only: sm_80+) --------------------
static __device__ __forceinline__ uint32_t smem_u32(const void* p) {
    uint32_t a;
    asm("{ .reg .u64 t; cvta.to.shared.u64 t, %1; cvt.u32.u64 %0, t; }"
        : "=r"(a) : "l"(p));
    return a;
}

static __device__ __forceinline__ void cpa16(uint32_t sa, const void* ga) {
    asm volatile("cp.async.cg.shared.global [%0], [%1], 16;"
                 :: "r"(sa), "l"(ga) : "memory");
}
#define CP_COMMIT() asm volatile("cp.async.commit_group;" ::: "memory")
#define CP_WAIT(n)  asm volatile("cp.async.wait_group %0;" :: "n"(n) : "memory")

static __device__ __forceinline__ void ldsm_x4(uint32_t* r, uint32_t addr) {
    asm volatile("ldmatrix.sync.aligned.m8n8.x4.shared.b16 {%0,%1,%2,%3}, [%4];"
                 : "=r"(r[0]), "=r"(r[1]), "=r"(r[2]), "=r"(r[3]) : "r"(addr));
}

static __device__ __forceinline__ void mma_fp16(float* d, const uint32_t* a, const uint32_t* b) {
    asm volatile(
        "mma.sync.aligned.m16n8k16.row.col.f32.f16.f16.f32 "
        "{%0,%1,%2,%3}, {%4,%5,%6,%7}, {%8,%9}, {%0,%1,%2,%3};"
        : "+f"(d[0]), "+f"(d[1]), "+f"(d[2]), "+f"(d[3])
        : "r"(a[0]), "r"(a[1]), "r"(a[2]), "r"(a[3]), "r"(b[0]), "r"(b[1]));
}

// ---------------- kernel 1: A build as shifted-image copies + W expand -------
// Per batch, A_flat[f*1024 + l] = U[f][l];  U[ci*9 + p] is image x[b][ci]
// shifted by (di-1, dj-1) with zero borders.  smem image padded to stride 33
// floats so lane-varying-row access is bank-conflict-free.
// Blocks [0, 2048)        : (b, ci) image -> 9 shifted fp16 copies
// Blocks [2048, 2048+512) : W row n = blk - 2048
#define IMG_PAD 33
__global__ void __launch_bounds__(288) build_aw_kernel(
    const float* __restrict__ x, const float* __restrict__ w)
{
    const int tt = threadIdx.x;
    if (blockIdx.x < 2048) {
        __shared__ float s_img[32 * IMG_PAD];
        const int b = blockIdx.x >> 8, ci = blockIdx.x & 255;
        if (tt < 256) {
            const int r = tt >> 3, c = (tt & 7) * 4;
            float4 v = *(const float4*)(x + ((((size_t)b << 8) + ci) << 10) + (r << 5) + c);
            float* d = s_img + r * IMG_PAD + c;
            d[0] = v.x; d[1] = v.y; d[2] = v.z; d[3] = v.w;   // (r+c) mod 32 distinct -> conflict-free
        }
        __syncthreads();

        const int p = tt >> 5;              // 0..8 shift pair
        const int hh = tt & 31;             // output row
        const int di = (p * 11) >> 5;       // p/3
        const int dj = p - di * 3;
        const int f = ci * 9 + p;
        const int sr = hh + di - 1;         // source row

        __half hv[32];
        if ((unsigned)sr < 32u) {
            const float* srow = s_img + sr * IMG_PAD;
#pragma unroll
            for (int ww = 0; ww < 32; ww++) {
                int sc = ww + dj - 1;
                float v = ((unsigned)sc < 32u) ? srow[sc] : 0.f;
                hv[ww] = __float2half_rn(v);
            }
        } else {
#pragma unroll
            for (int ww = 0; ww < 32; ww++) hv[ww] = __float2half_rn(0.f);
        }
        uint4* dst = (uint4*)(g_A + (size_t)b * ABATCH + (size_t)f * 1024 + (hh << 5));
#pragma unroll
        for (int qx = 0; qx < 4; qx++) dst[qx] = ((uint4*)hv)[qx];
    } else {
        const int n = blockIdx.x - 2048;     // 0..511
        const int q = tt >> 3;               // k-block index 0..35
        const int kk0 = (tt & 7) * 8;        // k within block, 8 at a time
        const int p = n >> 6, nn = n & 63;
        const float* wb = w + (p * 36 + q) * 64;
        __half2 h[4];
#pragma unroll
        for (int e = 0; e < 4; e++) {
            float v0 = wb[(nn - (kk0 + 2 * e)) & 63];
            float v1 = wb[(nn - (kk0 + 2 * e + 1)) & 63];
            h[e] = __floats2half2_rn(v0, v1);
        }
        *(uint4*)(g_W + (size_t)n * KDIM + q * 64 + kk0) = *(uint4*)h;
    }
}

// ---------------- kernel 2: single fp16 mma.sync GEMM (R8 best config) -------
// C[8192,512] = A * W^T.  CTA tile 128x128, K-chunk 64, 256 threads
// (8 warps, warp grid 4x2, warp tile 32x64).  3-stage cp.async pipeline,
// one barrier per chunk.  2 CTAs/SM.
#define OFF_A 0
#define OFF_B 16384
#define STAGE_BYTES 32768
#define NSTAGE 3
#define SMEM_DYN (NSTAGE * STAGE_BYTES + 1024)   // 99328

// smem rows of 64 fp16 = 128B, XOR-swizzled at 16B granularity:
//   phys(row, kb) = row*128 + ((kb ^ (row & 7)) << 4),  kb = 0..7
static __device__ __forceinline__ void load_stage(
    uint32_t sb,
    const __half* __restrict__ gA, const __half* __restrict__ gB,
    int chunk, int tid)
{
    const int ko = chunk * 64;
#pragma unroll
    for (int it = 0; it < 4; it++) {          // A: 128 rows x 8 chunks = 1024
        int i = it * 256 + tid;
        int row = i >> 3, kb = i & 7;
        uint32_t soff = (uint32_t)(row * 128 + ((kb ^ (row & 7)) << 4));
        cpa16(sb + OFF_A + soff, gA + (size_t)row * KDIM + ko + kb * 8);
    }
#pragma unroll
    for (int it = 0; it < 4; it++) {          // B: 128 rows x 8 chunks = 1024
        int i = it * 256 + tid;
        int row = i >> 3, kb = i & 7;
        uint32_t soff = (uint32_t)(row * 128 + ((kb ^ (row & 7)) << 4));
        cpa16(sb + OFF_B + soff, gB + (size_t)row * KDIM + ko + kb * 8);
    }
}

__global__ void __launch_bounds__(256, 2) gemm_kernel(float* __restrict__ out)
{
    extern __shared__ char dsm[];
    const int tid = threadIdx.x, wid = tid >> 5, lid = tid & 31;
    const int mtile = blockIdx.x;   // 0..63
    const int ntile = blockIdx.y;   // 0..3
    const int wm = wid & 3;         // m-quadrant: rows wm*32..+32
    const int wn = wid >> 2;        // n-half: cols wn*64..+64

    uint32_t dyn_base = smem_u32(dsm);
    uint32_t sm0 = (dyn_base + 1023u) & ~1023u;   // 1KB align

    const __half* gA = g_A + (size_t)mtile * 128 * KDIM;
    const __half* gB = g_W + (size_t)ntile * 128 * KDIM;

    float acc[2][8][4];
#pragma unroll
    for (int a = 0; a < 2; a++)
#pragma unroll
        for (int b = 0; b < 8; b++)
#pragma unroll
            for (int c = 0; c < 4; c++) acc[a][b][c] = 0.f;

    // ldmatrix lane addressing (fixed per thread)
    const int rowA_l = (lid & 15);                     // + wm*32 + mt*16
    const int halfA  = lid >> 4;
    const int rowB_l = (lid & 7) + ((lid & 16) >> 1);  // + wn*64 + g*16
    const int halfB  = (lid >> 3) & 1;

    // prologue: prefetch chunks 0 and 1
    load_stage(sm0, gA, gB, 0, tid);
    CP_COMMIT();
    load_stage(sm0 + STAGE_BYTES, gA, gB, 1, tid);
    CP_COMMIT();

    int stage = 0;
    for (int i = 0; i < NCHUNKS; i++) {
        if (i < NCHUNKS - 1) CP_WAIT(1); else CP_WAIT(0);
        __syncthreads();   // buffer i published; also protects stage reloaded below

        // prefetch chunk i+2 into the stage last read at iteration i-1
        if (i + 2 < NCHUNKS) {
            int ps = stage + 2; if (ps >= NSTAGE) ps -= NSTAGE;
            load_stage(sm0 + (uint32_t)ps * STAGE_BYTES, gA, gB, i + 2, tid);
            CP_COMMIT();
        }

        const uint32_t sb = sm0 + (uint32_t)stage * STAGE_BYTES;
        const uint32_t baseA = sb + OFF_A, baseB = sb + OFF_B;

#pragma unroll
        for (int j = 0; j < 4; j++) {
            uint32_t aF[2][4], bF[4][4];
#pragma unroll
            for (int mt = 0; mt < 2; mt++) {
                int row = wm * 32 + mt * 16 + rowA_l;
                ldsm_x4(aF[mt], baseA + row * 128 + (((j * 2 + halfA) ^ (row & 7)) << 4));
            }
#pragma unroll
            for (int g = 0; g < 4; g++) {
                int row = wn * 64 + g * 16 + rowB_l;
                ldsm_x4(bF[g], baseB + row * 128 + (((j * 2 + halfB) ^ (row & 7)) << 4));
            }
#pragma unroll
            for (int mt = 0; mt < 2; mt++)
#pragma unroll
                for (int nt = 0; nt < 8; nt++)
                    mma_fp16(acc[mt][nt], aF[mt], &bF[nt >> 1][(nt & 1) * 2]);
        }

        if (++stage == NSTAGE) stage = 0;
    }

    // ---------------- epilogue: direct transpose scatter ----------------------
    const int lr = lid >> 2, lc = (lid & 3) * 2;
#pragma unroll
    for (int mt = 0; mt < 2; mt++) {
#pragma unroll
        for (int part = 0; part < 2; part++) {
            int m = mtile * 128 + wm * 32 + mt * 16 + part * 8 + lr;
            int b = m >> 10, pix = m & 1023;
            float* ob = out + ((size_t)b << 19) + pix;   // + o*1024 per output chan
#pragma unroll
            for (int nt = 0; nt < 8; nt++) {
                int o = ntile * 128 + wn * 64 + nt * 8 + lc;
                ob[(size_t)o << 10]       = acc[mt][nt][part * 2 + 0];
                ob[(size_t)(o + 1) << 10] = acc[mt][nt][part * 2 + 1];
            }
        }
    }
}

// ---------------- launch -----------------------------------------------------
extern "C" void kernel_launch(void* const* d_in, const int* in_sizes, int n_in,
                              void* d_out, int out_size)
{
    const float* x = (const float*)d_in[0];   // (8,256,32,32)
    const float* w = (const float*)d_in[1];   // (8,36,64)
    float* out = (float*)d_out;               // (8,512,32,32)

    cudaFuncSetAttribute(gemm_kernel, cudaFuncAttributeMaxDynamicSharedMemorySize, SMEM_DYN);

    build_aw_kernel<<<2048 + NDIM, 288>>>(x, w);
    gemm_kernel<<<dim3(64, 4), 256, SMEM_DYN>>>(out);
}